// round 10
// baseline (speedup 1.0000x reference)
#include <cuda_runtime.h>
#include <cstdint>

// Problem shape (fixed by the dataset):
//   x:       (4, 2048, 4096) fp32  -> M=8192, K=4096 row-major
//   qweight: (512, 11008)   int32  -> 8 int4 nibbles per int32 along K
//   scales:  (32, 11008)    fp32   -> per-group(128) per-out-channel
//   out:     (4, 2048, 11008) fp32
static constexpr int M_DIM = 8192;
static constexpr int K_DIM = 4096;
static constexpr int N_DIM = 11008;

static constexpr int BM = 128;
static constexpr int BN = 256;
static constexpr int BK = 64;
static constexpr int NTH = 512;              // 16 warps: 2(m) x 8(n), tile 64x32
static constexpr int K_ITERS = K_DIM / BK;   // 64

// Tiles "outer x k", stride 68 floats (272B rows):
//   frag LDS bank = (4g + t) % 32 (distinct); STS.128 phase banks {4c..4c+3}.
static constexpr int STRIDE  = BK + 4;             // 68
static constexpr int A_ELEMS = BM * STRIDE;        // 8704 floats / buffer
static constexpr int B_ELEMS = BN * STRIDE;        // 17408 floats / buffer
static constexpr int SMEM_BYTES = 2 * (A_ELEMS + B_ELEMS) * 4;  // 208896

__device__ __forceinline__ uint32_t smem_u32(const void* p) {
    uint32_t a;
    asm("{ .reg .u64 t; cvta.to.shared.u64 t, %1; cvt.u32.u64 %0, t; }"
        : "=r"(a) : "l"(p));
    return a;
}
__device__ __forceinline__ void cp16(uint32_t dst, const void* src) {
    asm volatile("cp.async.cg.shared.global [%0], [%1], 16;"
                 :: "r"(dst), "l"(src));
}
// fp32 -> tf32 round-to-nearest in the integer domain (HMMA reads top 19 bits)
__device__ __forceinline__ float rn_tf32(float w) {
    return __uint_as_float(__float_as_uint(w) + 0x1000u);
}
__device__ __forceinline__ void mma_tf32(float c[4],
                                         uint32_t a0, uint32_t a1,
                                         uint32_t a2, uint32_t a3,
                                         uint32_t b0, uint32_t b1)
{
    asm volatile(
        "mma.sync.aligned.m16n8k8.row.col.f32.tf32.tf32.f32 "
        "{%0,%1,%2,%3}, {%4,%5,%6,%7}, {%8,%9}, {%0,%1,%2,%3};\n"
        : "+f"(c[0]), "+f"(c[1]), "+f"(c[2]), "+f"(c[3])
        : "r"(a0), "r"(a1), "r"(a2), "r"(a3), "r"(b0), "r"(b1));
}

__global__ __launch_bounds__(NTH, 1)
void int4_gemm_tf32_bk64_kernel(const float* __restrict__ X,
                                const int*   __restrict__ QW,
                                const float* __restrict__ SC,
                                float*       __restrict__ C)
{
    extern __shared__ float smem[];
    float* Asm = smem;                       // 2 x A_ELEMS
    float* Bsm = smem + 2 * A_ELEMS;         // 2 x B_ELEMS
    const uint32_t As_u32 = smem_u32(Asm);

    const int tid  = threadIdx.x;
    const int wid  = tid >> 5;
    const int lane = tid & 31;
    const int g    = lane >> 2;
    const int t    = lane & 3;
    const int wm   = wid >> 3;               // 0..1
    const int wn   = wid & 7;                // 0..7

    const int m0 = blockIdx.y * BM;
    const int n0 = blockIdx.x * BN;

    // ---- accumulators: warp 64x32 -> 4 x 4 x 4 = 64 regs -------------------
    float acc[4][4][4];
    #pragma unroll
    for (int i = 0; i < 4; i++)
        #pragma unroll
        for (int j = 0; j < 4; j++)
            #pragma unroll
            for (int r = 0; r < 4; r++) acc[i][j][r] = 0.0f;

    // ---- producer mappings ---------------------------------------------------
    // A: thread -> row tid>>2 (0..127), chunk (tid&3)*16 floats -> 4 x cp16
    const int arow   = tid >> 2;
    const int achunk = (tid & 3) * 16;
    const float* Xrow = X + (size_t)(m0 + arow) * K_DIM + achunk;
    const uint32_t a_dst0 = As_u32 + (uint32_t)(arow * STRIDE + achunk) * 4u;

    // B: thread -> column n0 + (tid & 255), k-half (tid >> 8): 4 qweight rows
    const int bcol = tid & 255;
    const int half = tid >> 8;                // 0/1 -> k local 32h..32h+31
    const int*   QWp = QW + n0 + bcol;
    const float* SCp = SC + n0 + bcol;

    int   qv[4];
    float s;

    // ---- prologue: stage + commit tile 0 --------------------------------------
    {
        #pragma unroll
        for (int c = 0; c < 4; c++)
            cp16(a_dst0 + c * 16u, Xrow + c * 4);
        asm volatile("cp.async.commit_group;");

        #pragma unroll
        for (int q = 0; q < 4; q++)
            qv[q] = QWp[(size_t)(half * 4 + q) * N_DIM];
        s = SCp[0];

        float* bp = Bsm + bcol * STRIDE + half * 32;
        #pragma unroll
        for (int q = 0; q < 4; q++) {
            const uint32_t w = (uint32_t)qv[q];
            float o[8];
            #pragma unroll
            for (int j = 0; j < 8; j++) {
                float fv = __uint_as_float(0x4B000000u | ((w >> (4 * j)) & 15u));
                o[j] = rn_tf32((fv - 8388616.0f) * s);
            }
            *reinterpret_cast<float4*>(bp + q * 8)     = make_float4(o[0], o[1], o[2], o[3]);
            *reinterpret_cast<float4*>(bp + q * 8 + 4) = make_float4(o[4], o[5], o[6], o[7]);
        }
        asm volatile("cp.async.wait_group 0;" ::: "memory");
        __syncthreads();
    }

    // ---- main loop --------------------------------------------------------------
    for (int iter = 0; iter < K_ITERS; iter++) {
        const int buf = iter & 1;
        const int nb  = buf ^ 1;
        const bool more = (iter + 1 < K_ITERS);

        // stage next tile: A via cp.async, B qwords via LDG into regs
        if (more) {
            const float* xp = Xrow + (iter + 1) * BK;
            const uint32_t ad = a_dst0 + (uint32_t)(nb * A_ELEMS) * 4u;
            #pragma unroll
            for (int c = 0; c < 4; c++)
                cp16(ad + c * 16u, xp + c * 4);
            asm volatile("cp.async.commit_group;");

            const int krow = (iter + 1) * 8 + half * 4;
            #pragma unroll
            for (int q = 0; q < 4; q++)
                qv[q] = QWp[(size_t)(krow + q) * N_DIM];
            s = SCp[(size_t)((iter + 1) >> 1) * N_DIM];
        }

        // ---- compute on current buffer: 8 x k8 steps ----------------------------
        {
            const float* Ap = Asm + buf * A_ELEMS + (wm * 64 + g) * STRIDE + t;
            const float* Bp = Bsm + buf * B_ELEMS + (wn * 32 + g) * STRIDE + t;

            #pragma unroll
            for (int kk = 0; kk < 8; kk++) {
                const int kb = kk * 8;
                uint32_t a[4][4];
                #pragma unroll
                for (int i = 0; i < 4; i++) {
                    const float* ar = Ap + i * 16 * STRIDE + kb;
                    a[i][0] = __float_as_uint(ar[0]);
                    a[i][1] = __float_as_uint(ar[8 * STRIDE]);
                    a[i][2] = __float_as_uint(ar[4]);
                    a[i][3] = __float_as_uint(ar[8 * STRIDE + 4]);
                }
                uint32_t b[4][2];
                #pragma unroll
                for (int j = 0; j < 4; j++) {
                    const float* br = Bp + j * 8 * STRIDE + kb;
                    b[j][0] = __float_as_uint(br[0]);
                    b[j][1] = __float_as_uint(br[4]);
                }
                #pragma unroll
                for (int i = 0; i < 4; i++)
                    #pragma unroll
                    for (int j = 0; j < 4; j++)
                        mma_tf32(acc[i][j], a[i][0], a[i][1], a[i][2], a[i][3],
                                 b[j][0], b[j][1]);
            }
        }

        // ---- dequant next B tile into the other buffer --------------------------
        if (more) {
            float* bp = Bsm + nb * B_ELEMS + bcol * STRIDE + half * 32;
            #pragma unroll
            for (int q = 0; q < 4; q++) {
                const uint32_t w = (uint32_t)qv[q];
                float o[8];
                #pragma unroll
                for (int j = 0; j < 8; j++) {
                    float fv = __uint_as_float(0x4B000000u | ((w >> (4 * j)) & 15u));
                    o[j] = rn_tf32((fv - 8388616.0f) * s);
                }
                *reinterpret_cast<float4*>(bp + q * 8)     = make_float4(o[0], o[1], o[2], o[3]);
                *reinterpret_cast<float4*>(bp + q * 8 + 4) = make_float4(o[4], o[5], o[6], o[7]);
            }
            asm volatile("cp.async.wait_group 0;" ::: "memory");
        }
        __syncthreads();
    }

    // ---- writeback (m16n8k8 C layout) ------------------------------------------
    #pragma unroll
    for (int i = 0; i < 4; i++) {
        int row = m0 + wm * 64 + i * 16 + g;
        #pragma unroll
        for (int j = 0; j < 4; j++) {
            int col = n0 + wn * 32 + j * 8 + 2 * t;
            *reinterpret_cast<float2*>(&C[(size_t)row * N_DIM + col]) =
                make_float2(acc[i][j][0], acc[i][j][1]);
            *reinterpret_cast<float2*>(&C[(size_t)(row + 8) * N_DIM + col]) =
                make_float2(acc[i][j][2], acc[i][j][3]);
        }
    }
}

extern "C" void kernel_launch(void* const* d_in, const int* in_sizes, int n_in,
                              void* d_out, int out_size)
{
    const float* x   = (const float*)d_in[0];
    const int*   qw  = (const int*)d_in[1];
    const float* sc  = (const float*)d_in[2];
    float*       out = (float*)d_out;

    cudaFuncSetAttribute(int4_gemm_tf32_bk64_kernel,
                         cudaFuncAttributeMaxDynamicSharedMemorySize, SMEM_BYTES);

    dim3 grid(N_DIM / BN, M_DIM / BM);  // (43, 64)
    int4_gemm_tf32_bk64_kernel<<<grid, NTH, SMEM_BYTES>>>(x, qw, sc, out);
}

// round 11
// speedup vs baseline: 1.1148x; 1.1148x over previous
#include <cuda_runtime.h>
#include <cstdint>

// Problem shape (fixed by the dataset):
//   x:       (4, 2048, 4096) fp32  -> M=8192, K=4096 row-major
//   qweight: (512, 11008)   int32  -> 8 int4 nibbles per int32 along K
//   scales:  (32, 11008)    fp32   -> per-group(128) per-out-channel
//   out:     (4, 2048, 11008) fp32
static constexpr int M_DIM = 8192;
static constexpr int K_DIM = 4096;
static constexpr int N_DIM = 11008;

static constexpr int BM = 128;
static constexpr int BN = 256;
static constexpr int BK = 32;
static constexpr int NTH = 512;              // 16 warps: 2(m) x 8(n), tile 64x32
static constexpr int K_ITERS = K_DIM / BK;   // 128

// Tiles "outer x k", stride 36 floats (144B rows).
//   LDSM: 8 rows start banks {4r} -> all 32 banks, conflict-free.
static constexpr int STRIDE  = BK + 4;             // 36
static constexpr int A_ELEMS = BM * STRIDE;        // 4608 floats / buffer
static constexpr int B_ELEMS = BN * STRIDE;        // 9216 floats / buffer
static constexpr int SMEM_BYTES = 2 * (A_ELEMS + B_ELEMS) * 4;  // 110592

__device__ __forceinline__ uint32_t smem_u32(const void* p) {
    uint32_t a;
    asm("{ .reg .u64 t; cvta.to.shared.u64 t, %1; cvt.u32.u64 %0, t; }"
        : "=r"(a) : "l"(p));
    return a;
}
__device__ __forceinline__ void cp16(uint32_t dst, const void* src) {
    asm volatile("cp.async.cg.shared.global [%0], [%1], 16;"
                 :: "r"(dst), "l"(src));
}
// fp32 -> tf32 round-to-nearest in the integer domain (HMMA reads top 19 bits)
__device__ __forceinline__ float rn_tf32(float w) {
    return __uint_as_float(__float_as_uint(w) + 0x1000u);
}
__device__ __forceinline__ void ldsm_x4(uint32_t& r0, uint32_t& r1,
                                        uint32_t& r2, uint32_t& r3,
                                        uint32_t addr)
{
    asm volatile("ldmatrix.sync.aligned.m8n8.x4.shared.b16 {%0,%1,%2,%3}, [%4];"
                 : "=r"(r0), "=r"(r1), "=r"(r2), "=r"(r3) : "r"(addr));
}
__device__ __forceinline__ void mma_tf32(float c[4],
                                         uint32_t a0, uint32_t a1,
                                         uint32_t a2, uint32_t a3,
                                         uint32_t b0, uint32_t b1)
{
    asm volatile(
        "mma.sync.aligned.m16n8k8.row.col.f32.tf32.tf32.f32 "
        "{%0,%1,%2,%3}, {%4,%5,%6,%7}, {%8,%9}, {%0,%1,%2,%3};\n"
        : "+f"(c[0]), "+f"(c[1]), "+f"(c[2]), "+f"(c[3])
        : "r"(a0), "r"(a1), "r"(a2), "r"(a3), "r"(b0), "r"(b1));
}

__global__ __launch_bounds__(NTH, 1)
void int4_gemm_tf32_ldsm_kernel(const float* __restrict__ X,
                                const int*   __restrict__ QW,
                                const float* __restrict__ SC,
                                float*       __restrict__ C)
{
    extern __shared__ float smem[];
    float* Asm = smem;                       // 2 x A_ELEMS
    float* Bsm = smem + 2 * A_ELEMS;         // 2 x B_ELEMS
    const uint32_t As_u32 = smem_u32(Asm);
    const uint32_t Bs_u32 = As_u32 + 2u * A_ELEMS * 4u;

    const int tid  = threadIdx.x;
    const int wid  = tid >> 5;
    const int lane = tid & 31;
    const int g    = lane >> 2;
    const int t    = lane & 3;
    const int wm   = wid >> 3;               // 0..1
    const int wn   = wid & 7;                // 0..7

    const int m0 = blockIdx.y * BM;
    const int n0 = blockIdx.x * BN;

    // ---- per-lane LDSM base offsets (bytes) ---------------------------------
    // A matrices: m0..m3 = {rows+0,rows+8} x {k+0,k+4}; lane l -> matrix l>>3,
    //   row (l&7). a-frag regs come out as {a0,a1,a2,a3} directly.
    const uint32_t a_lds =
        (uint32_t)(((wm * 64) + (lane & 7) + ((lane >> 3) & 1) * 8) * STRIDE
                   + ((lane >> 4) & 1) * 4) * 4u;
    // B matrices: {n rows+0,+8} x {k+0,k+4} -> regs {b[j0][0],b[j0][1],
    //   b[j1][0],b[j1][1]} for an n16 pair.
    const uint32_t b_lds =
        (uint32_t)(((wn * 32) + (lane & 7) + ((lane >> 4) & 1) * 8) * STRIDE
                   + ((lane >> 3) & 1) * 4) * 4u;

    // ---- accumulators: warp 64x32 -> 4 x 4 x 4 = 64 regs --------------------
    float acc[4][4][4];
    #pragma unroll
    for (int i = 0; i < 4; i++)
        #pragma unroll
        for (int j = 0; j < 4; j++)
            #pragma unroll
            for (int r = 0; r < 4; r++) acc[i][j][r] = 0.0f;

    // ---- producer mappings ----------------------------------------------------
    // A: thread -> row tid>>2 (0..127), chunk (tid&3)*8 floats -> 2 x cp16
    const int arow   = tid >> 2;
    const int achunk = (tid & 3) * 8;
    const float* Xrow = X + (size_t)(m0 + arow) * K_DIM + achunk;
    const uint32_t a_dst0 = As_u32 + (uint32_t)(arow * STRIDE + achunk) * 4u;

    // B: thread -> column n0 + (tid & 255), k-half (tid >> 8) of the 32-k tile
    const int bcol = tid & 255;
    const int half = tid >> 8;                // 0/1 -> qweight rows 2h, 2h+1
    const int*   QWp = QW + n0 + bcol;
    const float* SCp = SC + n0 + bcol;

    int   qv[2];
    float s;

    // ---- prologue: stage + commit tile 0 ----------------------------------------
    {
        cp16(a_dst0,       Xrow);
        cp16(a_dst0 + 16u, Xrow + 4);
        asm volatile("cp.async.commit_group;");

        qv[0] = QWp[(size_t)(half * 2)     * N_DIM];
        qv[1] = QWp[(size_t)(half * 2 + 1) * N_DIM];
        s     = SCp[0];

        float* bp = Bsm + bcol * STRIDE + half * 16;
        #pragma unroll
        for (int qq = 0; qq < 2; qq++) {
            const uint32_t q = (uint32_t)qv[qq];
            float o[8];
            #pragma unroll
            for (int j = 0; j < 8; j++) {
                float fv = __uint_as_float(0x4B000000u | ((q >> (4 * j)) & 15u));
                o[j] = rn_tf32((fv - 8388616.0f) * s);
            }
            *reinterpret_cast<float4*>(bp + qq * 8)     = make_float4(o[0], o[1], o[2], o[3]);
            *reinterpret_cast<float4*>(bp + qq * 8 + 4) = make_float4(o[4], o[5], o[6], o[7]);
        }
        asm volatile("cp.async.wait_group 0;" ::: "memory");
        __syncthreads();
    }

    // ---- main loop ----------------------------------------------------------------
    for (int iter = 0; iter < K_ITERS; iter++) {
        const int buf = iter & 1;
        const int nb  = buf ^ 1;
        const bool more = (iter + 1 < K_ITERS);

        // stage next tile: A via cp.async, B qwords via LDG into regs
        if (more) {
            const float* xp = Xrow + (iter + 1) * BK;
            const uint32_t ad = a_dst0 + (uint32_t)(nb * A_ELEMS) * 4u;
            cp16(ad,       xp);
            cp16(ad + 16u, xp + 4);
            asm volatile("cp.async.commit_group;");

            const int krow = (iter + 1) * 4 + half * 2;
            qv[0] = QWp[(size_t)krow       * N_DIM];
            qv[1] = QWp[(size_t)(krow + 1) * N_DIM];
            s     = SCp[(size_t)((iter + 1) >> 2) * N_DIM];
        }

        // ---- compute on current buffer; dequant interleaved at kk=0 / kk=2 -----
        {
            const uint32_t Ab = As_u32 + (uint32_t)(buf * A_ELEMS) * 4u + a_lds;
            const uint32_t Bb = Bs_u32 + (uint32_t)(buf * B_ELEMS) * 4u + b_lds;
            float* bp_next = Bsm + nb * B_ELEMS + bcol * STRIDE + half * 16;

            #pragma unroll
            for (int kk = 0; kk < 4; kk++) {
                const uint32_t ko = (uint32_t)(kk * 8 * 4);

                uint32_t a[4][4];
                #pragma unroll
                for (int i = 0; i < 4; i++)
                    ldsm_x4(a[i][0], a[i][1], a[i][2], a[i][3],
                            Ab + (uint32_t)(i * 16 * STRIDE * 4) + ko);

                uint32_t b[2][4];
                #pragma unroll
                for (int jp = 0; jp < 2; jp++)
                    ldsm_x4(b[jp][0], b[jp][1], b[jp][2], b[jp][3],
                            Bb + (uint32_t)(jp * 16 * STRIDE * 4) + ko);

                #pragma unroll
                for (int i = 0; i < 4; i++)
                    #pragma unroll
                    for (int j = 0; j < 4; j++)
                        mma_tf32(acc[i][j],
                                 a[i][0], a[i][1], a[i][2], a[i][3],
                                 b[j >> 1][(j & 1) * 2],
                                 b[j >> 1][(j & 1) * 2 + 1]);

                // interleaved producer chunk: overlaps the tensor-busy window
                if (more && ((kk & 1) == 0)) {
                    const int qq = kk >> 1;
                    const uint32_t q = (uint32_t)qv[qq];
                    float o[8];
                    #pragma unroll
                    for (int j = 0; j < 8; j++) {
                        float fv = __uint_as_float(
                            0x4B000000u | ((q >> (4 * j)) & 15u));
                        o[j] = rn_tf32((fv - 8388616.0f) * s);
                    }
                    *reinterpret_cast<float4*>(bp_next + qq * 8) =
                        make_float4(o[0], o[1], o[2], o[3]);
                    *reinterpret_cast<float4*>(bp_next + qq * 8 + 4) =
                        make_float4(o[4], o[5], o[6], o[7]);
                }
            }
        }

        if (more)
            asm volatile("cp.async.wait_group 0;" ::: "memory");
        __syncthreads();
    }

    // ---- writeback (m16n8k8 C layout) ---------------------------------------------
    #pragma unroll
    for (int i = 0; i < 4; i++) {
        int row = m0 + wm * 64 + i * 16 + g;
        #pragma unroll
        for (int j = 0; j < 4; j++) {
            int col = n0 + wn * 32 + j * 8 + 2 * t;
            *reinterpret_cast<float2*>(&C[(size_t)row * N_DIM + col]) =
                make_float2(acc[i][j][0], acc[i][j][1]);
            *reinterpret_cast<float2*>(&C[(size_t)(row + 8) * N_DIM + col]) =
                make_float2(acc[i][j][2], acc[i][j][3]);
        }
    }
}

extern "C" void kernel_launch(void* const* d_in, const int* in_sizes, int n_in,
                              void* d_out, int out_size)
{
    const float* x   = (const float*)d_in[0];
    const int*   qw  = (const int*)d_in[1];
    const float* sc  = (const float*)d_in[2];
    float*       out = (float*)d_out;

    cudaFuncSetAttribute(int4_gemm_tf32_ldsm_kernel,
                         cudaFuncAttributeMaxDynamicSharedMemorySize, SMEM_BYTES);

    dim3 grid(N_DIM / BN, M_DIM / BM);  // (43, 64)
    int4_gemm_tf32_ldsm_kernel<<<grid, NTH, SMEM_BYTES>>>(x, qw, sc, out);
}

// round 12
// speedup vs baseline: 1.2782x; 1.1465x over previous
#include <cuda_runtime.h>
#include <cstdint>

// Problem shape (fixed by the dataset):
//   x:       (4, 2048, 4096) fp32  -> M=8192, K=4096 row-major
//   qweight: (512, 11008)   int32  -> 8 int4 nibbles per int32 along K
//   scales:  (32, 11008)    fp32   -> per-group(128) per-out-channel
//   out:     (4, 2048, 11008) fp32
static constexpr int M_DIM = 8192;
static constexpr int K_DIM = 4096;
static constexpr int N_DIM = 11008;

static constexpr int BM = 128;
static constexpr int BN = 256;
static constexpr int BK = 32;
static constexpr int NTH = 512;              // 16 warps: 2(m) x 8(n), tile 64x32
static constexpr int K_ITERS = K_DIM / BK;   // 128
static constexpr int STAGES = 4;
static constexpr int AHEAD = 2;              // produce tile i+2 at iter i

// Tiles "outer x k", stride 36 floats (144B rows).
//   LDSM: 8 rows start banks {4r} -> all 32 banks, conflict-free.
static constexpr int STRIDE  = BK + 4;             // 36
static constexpr int A_ELEMS = BM * STRIDE;        // 4608 floats / stage
static constexpr int B_ELEMS = BN * STRIDE;        // 9216 floats / stage
static constexpr int STAGE_F = A_ELEMS + B_ELEMS;  // 13824 floats
static constexpr int STAGE_B = STAGE_F * 4;        // 55296 bytes
// smem: [0,64) mbarriers, tile data from byte 128
static constexpr int SMEM_BYTES = 128 + STAGES * STAGE_B;  // 221312

__device__ __forceinline__ uint32_t smem_u32(const void* p) {
    uint32_t a;
    asm("{ .reg .u64 t; cvta.to.shared.u64 t, %1; cvt.u32.u64 %0, t; }"
        : "=r"(a) : "l"(p));
    return a;
}
__device__ __forceinline__ void cp16(uint32_t dst, const void* src) {
    asm volatile("cp.async.cg.shared.global [%0], [%1], 16;"
                 :: "r"(dst), "l"(src));
}
__device__ __forceinline__ void mbar_init(uint32_t m, uint32_t cnt) {
    asm volatile("mbarrier.init.shared.b64 [%0], %1;" :: "r"(m), "r"(cnt) : "memory");
}
__device__ __forceinline__ void mbar_arrive(uint32_t m) {
    asm volatile("mbarrier.arrive.shared.b64 _, [%0];" :: "r"(m) : "memory");
}
__device__ __forceinline__ void cp_arrive(uint32_t m) {
    asm volatile("cp.async.mbarrier.arrive.shared.b64 [%0];" :: "r"(m) : "memory");
}
__device__ __forceinline__ void mbar_wait(uint32_t mbar, uint32_t parity) {
    uint32_t done;
    asm volatile(
        "{\n\t"
        ".reg .pred p;\n\t"
        "mbarrier.try_wait.parity.acquire.cta.shared::cta.b64 p, [%1], %2;\n\t"
        "selp.b32 %0, 1, 0, p;\n\t"
        "}"
        : "=r"(done) : "r"(mbar), "r"(parity) : "memory");
    if (!done) {
        asm volatile(
            "{\n\t"
            ".reg .pred P1;\n\t"
            "WL_%=:\n\t"
            "mbarrier.try_wait.parity.acquire.cta.shared::cta.b64 P1, [%0], %1, 0x989680;\n\t"
            "@P1 bra.uni WD_%=;\n\t"
            "bra.uni WL_%=;\n\t"
            "WD_%=:\n\t"
            "}"
            :: "r"(mbar), "r"(parity) : "memory");
    }
}

// fp32 -> tf32 round-to-nearest in the integer domain (HMMA reads top 19 bits)
__device__ __forceinline__ float rn_tf32(float w) {
    return __uint_as_float(__float_as_uint(w) + 0x1000u);
}
__device__ __forceinline__ void ldsm_x4(uint32_t& r0, uint32_t& r1,
                                        uint32_t& r2, uint32_t& r3,
                                        uint32_t addr)
{
    asm volatile("ldmatrix.sync.aligned.m8n8.x4.shared.b16 {%0,%1,%2,%3}, [%4];"
                 : "=r"(r0), "=r"(r1), "=r"(r2), "=r"(r3) : "r"(addr));
}
__device__ __forceinline__ void mma_tf32(float c[4],
                                         uint32_t a0, uint32_t a1,
                                         uint32_t a2, uint32_t a3,
                                         uint32_t b0, uint32_t b1)
{
    asm volatile(
        "mma.sync.aligned.m16n8k8.row.col.f32.tf32.tf32.f32 "
        "{%0,%1,%2,%3}, {%4,%5,%6,%7}, {%8,%9}, {%0,%1,%2,%3};\n"
        : "+f"(c[0]), "+f"(c[1]), "+f"(c[2]), "+f"(c[3])
        : "r"(a0), "r"(a1), "r"(a2), "r"(a3), "r"(b0), "r"(b1));
}

__global__ __launch_bounds__(NTH, 1)
void int4_gemm_tf32_ring_kernel(const float* __restrict__ X,
                                const int*   __restrict__ QW,
                                const float* __restrict__ SC,
                                float*       __restrict__ C)
{
    extern __shared__ float smem[];
    const uint32_t sb = smem_u32(smem);
    float* data = smem + 32;                 // byte 128

    const int tid  = threadIdx.x;
    const int wid  = tid >> 5;
    const int lane = tid & 31;
    const int g    = lane >> 2;
    const int t    = lane & 3;
    const int wm   = wid >> 3;               // 0..1
    const int wn   = wid & 7;                // 0..7

    const int m0 = blockIdx.y * BM;
    const int n0 = blockIdx.x * BN;

    // mbarriers: full[s] = sb + 16s, empty[s] = sb + 16s + 8
    if (tid == 0) {
        #pragma unroll
        for (int s = 0; s < STAGES; s++) {
            mbar_init(sb + 16 * s,     NTH);  // full: explicit post-STS arrivals
            mbar_init(sb + 16 * s + 8, NTH);  // empty: consumer arrivals
        }
    }
    __syncthreads();

    // ---- per-lane LDSM base offsets (bytes), as validated in round 11 -------
    const uint32_t a_lds =
        (uint32_t)(((wm * 64) + (lane & 7) + ((lane >> 3) & 1) * 8) * STRIDE
                   + ((lane >> 4) & 1) * 4) * 4u;
    const uint32_t b_lds =
        (uint32_t)(((wn * 32) + (lane & 7) + ((lane >> 4) & 1) * 8) * STRIDE
                   + ((lane >> 3) & 1) * 4) * 4u;

    // ---- accumulators: warp 64x32 -> 4 x 4 x 4 = 64 regs ---------------------
    float acc[4][4][4];
    #pragma unroll
    for (int i = 0; i < 4; i++)
        #pragma unroll
        for (int j = 0; j < 4; j++)
            #pragma unroll
            for (int r = 0; r < 4; r++) acc[i][j][r] = 0.0f;

    // ---- producer mappings -----------------------------------------------------
    const int arow   = tid >> 2;
    const int achunk = (tid & 3) * 8;
    const float* Xrow = X + (size_t)(m0 + arow) * K_DIM + achunk;
    const uint32_t a_off = (uint32_t)(arow * STRIDE + achunk) * 4u;

    const int bcol = tid & 255;
    const int half = tid >> 8;                // 0/1 -> qweight rows 2h, 2h+1
    const int*   QWp = QW + n0 + bcol;
    const float* SCp = SC + n0 + bcol;
    const int b_off = A_ELEMS + bcol * STRIDE + half * 16;

    // ---- prologue: produce tiles 0 and 1 ----------------------------------------
    #pragma unroll
    for (int p = 0; p < AHEAD; p++) {
        const float* xp = Xrow + p * BK;
        const uint32_t ad = sb + 128u + (uint32_t)p * STAGE_B + a_off;
        cp16(ad,       xp);
        cp16(ad + 16u, xp + 4);
        cp_arrive(sb + 16 * p);
    }
    #pragma unroll
    for (int p = 0; p < AHEAD; p++) {
        const int krow = p * 4 + half * 2;
        const int   q0 = QWp[(size_t)krow       * N_DIM];
        const int   q1 = QWp[(size_t)(krow + 1) * N_DIM];
        const float sv = SCp[0];
        float* bp = data + p * STAGE_F + b_off;
        #pragma unroll
        for (int qq = 0; qq < 2; qq++) {
            const uint32_t q = (uint32_t)(qq ? q1 : q0);
            float o[8];
            #pragma unroll
            for (int j = 0; j < 8; j++) {
                float fv = __uint_as_float(0x4B000000u | ((q >> (4 * j)) & 15u));
                o[j] = rn_tf32((fv - 8388616.0f) * sv);
            }
            *reinterpret_cast<float4*>(bp + qq * 8)     = make_float4(o[0], o[1], o[2], o[3]);
            *reinterpret_cast<float4*>(bp + qq * 8 + 4) = make_float4(o[4], o[5], o[6], o[7]);
        }
        mbar_arrive(sb + 16 * p);   // full
    }

    // ---- cursors ------------------------------------------------------------------
    int cst = 0, cph = 0;           // consumer: full-wait
    int pst = AHEAD, pph = 1;       // producer: empty-wait (first-lap passes)

    // ---- main loop ------------------------------------------------------------------
    for (int i = 0; i < K_ITERS; i++) {
        const bool do_prod = (i + AHEAD < K_ITERS);

        int   qv[2];
        float sv = 0.0f;
        float* bp_next = nullptr;

        if (do_prod) {
            // q/scale LDGs for tile i+2 (L2-resident; hidden under kk 0-1)
            const int krow = (i + AHEAD) * 4 + half * 2;
            qv[0] = QWp[(size_t)krow       * N_DIM];
            qv[1] = QWp[(size_t)(krow + 1) * N_DIM];
            sv    = SCp[(size_t)((i + AHEAD) >> 2) * N_DIM];

            // stage free? (all warps consumed tile i-2)
            mbar_wait(sb + 16 * pst + 8, pph);

            // A tile for i+2 via cp.async; arrive folds into full on completion
            const float* xp = Xrow + (i + AHEAD) * BK;
            const uint32_t ad = sb + 128u + (uint32_t)pst * STAGE_B + a_off;
            cp16(ad,       xp);
            cp16(ad + 16u, xp + 4);
            cp_arrive(sb + 16 * pst);

            bp_next = data + pst * STAGE_F + b_off;
        }

        // wait current tile ready
        mbar_wait(sb + 16 * cst, cph);

        // ---- kk loop: LDSM + MMA, dequant interleaved at kk=0 / kk=2 ----------
        {
            const uint32_t stb = sb + 128u + (uint32_t)cst * STAGE_B;
            const uint32_t Ab  = stb + a_lds;
            const uint32_t Bb  = stb + (uint32_t)(A_ELEMS * 4) + b_lds;

            #pragma unroll
            for (int kk = 0; kk < 4; kk++) {
                const uint32_t ko = (uint32_t)(kk * 8 * 4);

                uint32_t a[4][4];
                #pragma unroll
                for (int ii = 0; ii < 4; ii++)
                    ldsm_x4(a[ii][0], a[ii][1], a[ii][2], a[ii][3],
                            Ab + (uint32_t)(ii * 16 * STRIDE * 4) + ko);

                uint32_t b[2][4];
                #pragma unroll
                for (int jp = 0; jp < 2; jp++)
                    ldsm_x4(b[jp][0], b[jp][1], b[jp][2], b[jp][3],
                            Bb + (uint32_t)(jp * 16 * STRIDE * 4) + ko);

                #pragma unroll
                for (int ii = 0; ii < 4; ii++)
                    #pragma unroll
                    for (int j = 0; j < 4; j++)
                        mma_tf32(acc[ii][j],
                                 a[ii][0], a[ii][1], a[ii][2], a[ii][3],
                                 b[j >> 1][(j & 1) * 2],
                                 b[j >> 1][(j & 1) * 2 + 1]);

                if (do_prod && ((kk & 1) == 0)) {
                    const int qq = kk >> 1;
                    const uint32_t q = (uint32_t)qv[qq];
                    float o[8];
                    #pragma unroll
                    for (int j = 0; j < 8; j++) {
                        float fv = __uint_as_float(
                            0x4B000000u | ((q >> (4 * j)) & 15u));
                        o[j] = rn_tf32((fv - 8388616.0f) * sv);
                    }
                    *reinterpret_cast<float4*>(bp_next + qq * 8) =
                        make_float4(o[0], o[1], o[2], o[3]);
                    *reinterpret_cast<float4*>(bp_next + qq * 8 + 4) =
                        make_float4(o[4], o[5], o[6], o[7]);
                }
            }
        }

        if (do_prod) {
            mbar_arrive(sb + 16 * pst);          // full (release; after STS)
            if (++pst == STAGES) { pst = 0; pph ^= 1; }
        }
        mbar_arrive(sb + 16 * cst + 8);          // empty (release; after LDSM)
        if (++cst == STAGES) { cst = 0; cph ^= 1; }
    }

    // ---- writeback (m16n8k8 C layout) ------------------------------------------------
    #pragma unroll
    for (int i = 0; i < 4; i++) {
        int row = m0 + wm * 64 + i * 16 + g;
        #pragma unroll
        for (int j = 0; j < 4; j++) {
            int col = n0 + wn * 32 + j * 8 + 2 * t;
            *reinterpret_cast<float2*>(&C[(size_t)row * N_DIM + col]) =
                make_float2(acc[i][j][0], acc[i][j][1]);
            *reinterpret_cast<float2*>(&C[(size_t)(row + 8) * N_DIM + col]) =
                make_float2(acc[i][j][2], acc[i][j][3]);
        }
    }
}

extern "C" void kernel_launch(void* const* d_in, const int* in_sizes, int n_in,
                              void* d_out, int out_size)
{
    const float* x   = (const float*)d_in[0];
    const int*   qw  = (const int*)d_in[1];
    const float* sc  = (const float*)d_in[2];
    float*       out = (float*)d_out;

    cudaFuncSetAttribute(int4_gemm_tf32_ring_kernel,
                         cudaFuncAttributeMaxDynamicSharedMemorySize, SMEM_BYTES);

    dim3 grid(N_DIM / BN, M_DIM / BM);  // (43, 64)
    int4_gemm_tf32_ring_kernel<<<grid, NTH, SMEM_BYTES>>>(x, qw, sc, out);
}

// round 13
// speedup vs baseline: 1.9831x; 1.5515x over previous
#include <cuda_runtime.h>
#include <cuda_fp16.h>
#include <cstdint>

// Problem shape (fixed by the dataset):
//   x:       (4, 2048, 4096) fp32  -> M=8192, K=4096 row-major
//   qweight: (512, 11008)   int32  -> 8 int4 nibbles per int32 along K
//   scales:  (32, 11008)    fp32   -> per-group(128) per-out-channel
//   out:     (4, 2048, 11008) fp32
static constexpr int M_DIM = 8192;
static constexpr int K_DIM = 4096;
static constexpr int N_DIM = 11008;

static constexpr int BM = 128;
static constexpr int BN = 256;
static constexpr int BK = 32;
static constexpr int NTH = 512;              // 16 warps: 2(m) x 8(n), tile 64x32
static constexpr int K_ITERS = K_DIM / BK;   // 128
static constexpr int STAGES = 4;
static constexpr int AHEAD = 2;

// fp16 tiles "outer x k": row = 32 fp16 + 8 pad = 40 fp16 = 80 B (20 banks).
// LDSM 8-row windows at banks {20r..20r+3} -> all 32 banks, conflict-free.
static constexpr int ROWB    = 80;
static constexpr int A_BYTES = BM * ROWB;            // 10240
static constexpr int B_BYTES = BN * ROWB;            // 20480
static constexpr int STAGE_B = A_BYTES + B_BYTES;    // 30720
// smem: [0,64) mbarriers, tile data from byte 128
static constexpr int SMEM_BYTES = 128 + STAGES * STAGE_B;  // 123008

__device__ __forceinline__ uint32_t smem_u32(const void* p) {
    uint32_t a;
    asm("{ .reg .u64 t; cvta.to.shared.u64 t, %1; cvt.u32.u64 %0, t; }"
        : "=r"(a) : "l"(p));
    return a;
}
__device__ __forceinline__ void mbar_init(uint32_t m, uint32_t cnt) {
    asm volatile("mbarrier.init.shared.b64 [%0], %1;" :: "r"(m), "r"(cnt) : "memory");
}
__device__ __forceinline__ void mbar_arrive(uint32_t m) {
    asm volatile("mbarrier.arrive.shared.b64 _, [%0];" :: "r"(m) : "memory");
}
__device__ __forceinline__ void mbar_wait(uint32_t mbar, uint32_t parity) {
    uint32_t done;
    asm volatile(
        "{\n\t"
        ".reg .pred p;\n\t"
        "mbarrier.try_wait.parity.acquire.cta.shared::cta.b64 p, [%1], %2;\n\t"
        "selp.b32 %0, 1, 0, p;\n\t"
        "}"
        : "=r"(done) : "r"(mbar), "r"(parity) : "memory");
    if (!done) {
        asm volatile(
            "{\n\t"
            ".reg .pred P1;\n\t"
            "WL_%=:\n\t"
            "mbarrier.try_wait.parity.acquire.cta.shared::cta.b64 P1, [%0], %1, 0x989680;\n\t"
            "@P1 bra.uni WD_%=;\n\t"
            "bra.uni WL_%=;\n\t"
            "WD_%=:\n\t"
            "}"
            :: "r"(mbar), "r"(parity) : "memory");
    }
}

__device__ __forceinline__ void ldsm_x4(uint32_t* r, uint32_t addr) {
    asm volatile("ldmatrix.sync.aligned.m8n8.x4.shared.b16 {%0,%1,%2,%3}, [%4];"
                 : "=r"(r[0]), "=r"(r[1]), "=r"(r[2]), "=r"(r[3]) : "r"(addr));
}
__device__ __forceinline__ void mma_f16(float c[4],
                                        uint32_t a0, uint32_t a1,
                                        uint32_t a2, uint32_t a3,
                                        uint32_t b0, uint32_t b1)
{
    asm volatile(
        "mma.sync.aligned.m16n8k16.row.col.f32.f16.f16.f32 "
        "{%0,%1,%2,%3}, {%4,%5,%6,%7}, {%8,%9}, {%0,%1,%2,%3};\n"
        : "+f"(c[0]), "+f"(c[1]), "+f"(c[2]), "+f"(c[3])
        : "r"(a0), "r"(a1), "r"(a2), "r"(a3), "r"(b0), "r"(b1));
}

__device__ __forceinline__ uint32_t hsub2(uint32_t a, uint32_t b) {
    uint32_t d;
    asm("sub.rn.f16x2 %0, %1, %2;" : "=r"(d) : "r"(a), "r"(b));
    return d;
}
__device__ __forceinline__ uint32_t hmul2(uint32_t a, uint32_t b) {
    uint32_t d;
    asm("mul.rn.f16x2 %0, %1, %2;" : "=r"(d) : "r"(a), "r"(b));
    return d;
}
// pack two fp32 -> fp16x2 {lo, hi}
__device__ __forceinline__ uint32_t packh2(float lo, float hi) {
    uint32_t d;
    asm("cvt.rn.f16x2.f32 %0, %1, %2;" : "=r"(d) : "f"(hi), "f"(lo));
    return d;
}
// dequant one qword (8 nibbles along k) -> 8 fp16 in k-order, scaled.
// (nib | 0x6400) = fp16(1024+v) exact; -1032 exact; *s rounds once.
__device__ __forceinline__ uint4 dequant8(uint32_t q, uint32_t s2) {
    const uint32_t M = 0x000F000Fu, MG = 0x64006400u, C = 0x64086408u;
    uint32_t t0 = (q & M) | MG;            // {v0, v4}
    uint32_t t1 = ((q >> 4)  & M) | MG;    // {v1, v5}
    uint32_t t2 = ((q >> 8)  & M) | MG;    // {v2, v6}
    uint32_t t3 = ((q >> 12) & M) | MG;    // {v3, v7}
    t0 = hmul2(hsub2(t0, C), s2);
    t1 = hmul2(hsub2(t1, C), s2);
    t2 = hmul2(hsub2(t2, C), s2);
    t3 = hmul2(hsub2(t3, C), s2);
    uint4 o;
    o.x = __byte_perm(t0, t1, 0x5410);     // {w0, w1}
    o.y = __byte_perm(t2, t3, 0x5410);     // {w2, w3}
    o.z = __byte_perm(t0, t1, 0x7632);     // {w4, w5}
    o.w = __byte_perm(t2, t3, 0x7632);     // {w6, w7}
    return o;
}
__device__ __forceinline__ uint32_t scale2h(float s) {
    unsigned short h = __half_as_ushort(__float2half_rn(s));
    return (uint32_t)h * 0x10001u;
}

__global__ __launch_bounds__(NTH, 1)
void int4_gemm_f16_ring_kernel(const float* __restrict__ X,
                               const int*   __restrict__ QW,
                               const float* __restrict__ SC,
                               float*       __restrict__ C)
{
    extern __shared__ char smem[];
    const uint32_t sb = smem_u32(smem);
    char* data = smem + 128;

    const int tid  = threadIdx.x;
    const int wid  = tid >> 5;
    const int lane = tid & 31;
    const int g    = lane >> 2;
    const int t    = lane & 3;
    const int wm   = wid >> 3;               // 0..1
    const int wn   = wid & 7;                // 0..7

    const int m0 = blockIdx.y * BM;
    const int n0 = blockIdx.x * BN;

    // mbarriers: full[s] = sb + 16s, empty[s] = sb + 16s + 8; 1 flip per use.
    if (tid == 0) {
        #pragma unroll
        for (int s = 0; s < STAGES; s++) {
            mbar_init(sb + 16 * s,     NTH);  // full: explicit post-STS arrivals
            mbar_init(sb + 16 * s + 8, NTH);  // empty: consumer arrivals
        }
    }
    __syncthreads();

    // ---- per-lane LDSM base offsets (bytes) ----------------------------------
    // matrices: {rows+0, rows+8} x {k bytes +0, +16}; lane l -> matrix l>>3,
    // row l&7. reg order = fragment order for m16n8k16.
    const uint32_t a_lds =
        (uint32_t)((wm * 64 + (lane & 7) + ((lane >> 3) & 1) * 8) * ROWB
                   + ((lane >> 4) & 1) * 16);
    const uint32_t b_lds =
        (uint32_t)((wn * 32 + (lane & 7) + ((lane >> 3) & 1) * 8) * ROWB
                   + ((lane >> 4) & 1) * 16);

    // ---- accumulators: warp 64x32 -> 4(m16) x 4(n8) x 4 = 64 regs -------------
    float acc[4][4][4];
    #pragma unroll
    for (int i = 0; i < 4; i++)
        #pragma unroll
        for (int j = 0; j < 4; j++)
            #pragma unroll
            for (int r = 0; r < 4; r++) acc[i][j][r] = 0.0f;

    // ---- producer mappings ------------------------------------------------------
    // A: thread -> row tid>>2, quarter (tid&3): 8 fp32 LDG -> 8 fp16 = 1 STS.128
    const int arow = tid >> 2;
    const int aq   = tid & 3;
    const float* Xrow = X + (size_t)(m0 + arow) * K_DIM + aq * 8;
    const uint32_t a_sts = (uint32_t)(arow * ROWB + aq * 16);

    // B: thread -> column n0+(tid&255), k-half (tid>>8): 2 qwords -> 2 STS.128
    const int bcol = tid & 255;
    const int bh   = tid >> 8;                // 0/1 -> qweight rows 2bh, 2bh+1
    const int*   QWp = QW + n0 + bcol;
    const float* SCp = SC + n0 + bcol;
    const uint32_t b_sts = (uint32_t)(A_BYTES + bcol * ROWB + bh * 32);

    // ---- prologue: produce tiles 0 and 1 ----------------------------------------
    #pragma unroll
    for (int p = 0; p < AHEAD; p++) {
        const float4* xp = reinterpret_cast<const float4*>(Xrow + p * BK);
        float4 va0 = xp[0], va1 = xp[1];

        const int krow = p * 4 + bh * 2;
        uint32_t q0 = (uint32_t)QWp[(size_t)krow       * N_DIM];
        uint32_t q1 = (uint32_t)QWp[(size_t)(krow + 1) * N_DIM];
        uint32_t s2 = scale2h(SCp[0]);        // tiles 0,1 in group 0

        char* stp = data + p * STAGE_B;
        *reinterpret_cast<uint4*>(stp + b_sts)      = dequant8(q0, s2);
        *reinterpret_cast<uint4*>(stp + b_sts + 16) = dequant8(q1, s2);

        uint4 ha;
        ha.x = packh2(va0.x, va0.y); ha.y = packh2(va0.z, va0.w);
        ha.z = packh2(va1.x, va1.y); ha.w = packh2(va1.z, va1.w);
        *reinterpret_cast<uint4*>(stp + a_sts) = ha;

        mbar_arrive(sb + 16 * p);   // full
    }

    // held q/scale for tile AHEAD (dequanted next loop iteration)
    uint32_t qh0, qh1;
    float sh;
    {
        const int krow = AHEAD * 4 + bh * 2;
        qh0 = (uint32_t)QWp[(size_t)krow       * N_DIM];
        qh1 = (uint32_t)QWp[(size_t)(krow + 1) * N_DIM];
        sh  = SCp[(size_t)(AHEAD >> 2) * N_DIM];
    }

    // ---- cursors -------------------------------------------------------------------
    int cst = 0, cph = 0;           // consumer: full-wait
    int pst = AHEAD, pph = 1;       // producer: empty-wait (first-lap passes)

    // ---- main loop -------------------------------------------------------------------
    for (int i = 0; i < K_ITERS; i++) {
        const bool do_prod = (i + AHEAD < K_ITERS);

        float4 va0, va1;
        char* pstage = nullptr;
        uint32_t s2 = 0;
        if (do_prod) {
            const float4* xp =
                reinterpret_cast<const float4*>(Xrow + (i + AHEAD) * BK);
            va0 = xp[0]; va1 = xp[1];          // LDG early; used after kk loop
            s2 = scale2h(sh);
            mbar_wait(sb + 16 * pst + 8, pph); // stage empty?
            pstage = data + pst * STAGE_B;
        }

        // prefetch q/scale for tile i+3 (one full iteration of LDG cover)
        uint32_t qn0 = 0, qn1 = 0;
        float sn = 0.0f;
        if (i + AHEAD + 1 < K_ITERS) {
            const int krow = (i + AHEAD + 1) * 4 + bh * 2;
            qn0 = (uint32_t)QWp[(size_t)krow       * N_DIM];
            qn1 = (uint32_t)QWp[(size_t)(krow + 1) * N_DIM];
            sn  = SCp[(size_t)((i + AHEAD + 1) >> 2) * N_DIM];
        }

        mbar_wait(sb + 16 * cst, cph);         // current tile ready

        const uint32_t stb = sb + 128u + (uint32_t)(cst * STAGE_B);
        const uint32_t Ab  = stb + a_lds;
        const uint32_t Bb  = stb + (uint32_t)A_BYTES + b_lds;

        #pragma unroll
        for (int kk = 0; kk < 2; kk++) {       // two k16 steps
            const uint32_t ko = (uint32_t)(kk * 32);

            uint32_t a[4][4];
            #pragma unroll
            for (int ii = 0; ii < 4; ii++)
                ldsm_x4(a[ii], Ab + (uint32_t)(ii * 16 * ROWB) + ko);

            uint32_t b[2][4];
            #pragma unroll
            for (int jp = 0; jp < 2; jp++)
                ldsm_x4(b[jp], Bb + (uint32_t)(jp * 16 * ROWB) + ko);

            #pragma unroll
            for (int ii = 0; ii < 4; ii++)
                #pragma unroll
                for (int jp = 0; jp < 2; jp++)
                    #pragma unroll
                    for (int j2 = 0; j2 < 2; j2++)
                        mma_f16(acc[ii][jp * 2 + j2],
                                a[ii][0], a[ii][1], a[ii][2], a[ii][3],
                                b[jp][j2], b[jp][2 + j2]);

            // interleaved B dequant for tile i+2 (one qword per kk)
            if (do_prod) {
                uint4 o = dequant8(kk ? qh1 : qh0, s2);
                *reinterpret_cast<uint4*>(pstage + b_sts + kk * 16) = o;
            }
        }

        if (do_prod) {
            uint4 ha;                           // A convert + store (LDG now landed)
            ha.x = packh2(va0.x, va0.y); ha.y = packh2(va0.z, va0.w);
            ha.z = packh2(va1.x, va1.y); ha.w = packh2(va1.z, va1.w);
            *reinterpret_cast<uint4*>(pstage + a_sts) = ha;

            mbar_arrive(sb + 16 * pst);         // full (release)
            if (++pst == STAGES) { pst = 0; pph ^= 1; }
            qh0 = qn0; qh1 = qn1; sh = sn;
        }
        mbar_arrive(sb + 16 * cst + 8);         // empty (release)
        if (++cst == STAGES) { cst = 0; cph ^= 1; }
    }

    // ---- writeback (m16n8k16 C layout == m16n8k8) ----------------------------------
    #pragma unroll
    for (int i = 0; i < 4; i++) {
        int row = m0 + wm * 64 + i * 16 + g;
        #pragma unroll
        for (int j = 0; j < 4; j++) {
            int col = n0 + wn * 32 + j * 8 + 2 * t;
            *reinterpret_cast<float2*>(&C[(size_t)row * N_DIM + col]) =
                make_float2(acc[i][j][0], acc[i][j][1]);
            *reinterpret_cast<float2*>(&C[(size_t)(row + 8) * N_DIM + col]) =
                make_float2(acc[i][j][2], acc[i][j][3]);
        }
    }
}

extern "C" void kernel_launch(void* const* d_in, const int* in_sizes, int n_in,
                              void* d_out, int out_size)
{
    const float* x   = (const float*)d_in[0];
    const int*   qw  = (const int*)d_in[1];
    const float* sc  = (const float*)d_in[2];
    float*       out = (float*)d_out;

    cudaFuncSetAttribute(int4_gemm_f16_ring_kernel,
                         cudaFuncAttributeMaxDynamicSharedMemorySize, SMEM_BYTES);

    dim3 grid(N_DIM / BN, M_DIM / BM);  // (43, 64)
    int4_gemm_f16_ring_kernel<<<grid, NTH, SMEM_BYTES>>>(x, qw, sc, out);
}

// round 15
// speedup vs baseline: 1.9851x; 1.0010x over previous
#include <cuda_runtime.h>
#include <cuda_fp16.h>
#include <cstdint>

// Problem shape (fixed by the dataset):
//   x:       (4, 2048, 4096) fp32  -> M=8192, K=4096 row-major
//   qweight: (512, 11008)   int32  -> 8 int4 nibbles per int32 along K
//   scales:  (32, 11008)    fp32   -> per-group(128) per-out-channel
//   out:     (4, 2048, 11008) fp32
static constexpr int M_DIM = 8192;
static constexpr int K_DIM = 4096;
static constexpr int N_DIM = 11008;

static constexpr int BM = 128;
static constexpr int BN = 256;
static constexpr int BK = 32;
static constexpr int NTH = 512;              // 16 warps: 2(m) x 8(n), tile 64x32
static constexpr int K_ITERS = K_DIM / BK;   // 128
static constexpr int STAGES = 4;
static constexpr int AHEAD = 2;

// fp16 tiles "outer x k": row = 32 fp16 + 8 pad = 40 fp16 = 80 B (20 banks).
// LDSM 8-row windows at banks {20r..20r+3} -> all 32 banks, conflict-free.
static constexpr int ROWB    = 80;
static constexpr int A_BYTES = BM * ROWB;            // 10240
static constexpr int B_BYTES = BN * ROWB;            // 20480
static constexpr int STAGE_B = A_BYTES + B_BYTES;    // 30720
// smem: [0,64) mbarriers, tile data from byte 128
static constexpr int SMEM_BYTES = 128 + STAGES * STAGE_B;  // 123008

// Pre-converted fp16 copy of X (static scratch; allocation-free).
__device__ __half A_half[(size_t)M_DIM * K_DIM];

__device__ __forceinline__ uint32_t smem_u32(const void* p) {
    uint32_t a;
    asm("{ .reg .u64 t; cvta.to.shared.u64 t, %1; cvt.u32.u64 %0, t; }"
        : "=r"(a) : "l"(p));
    return a;
}
__device__ __forceinline__ void cp16(uint32_t dst, const void* src) {
    asm volatile("cp.async.cg.shared.global [%0], [%1], 16;"
                 :: "r"(dst), "l"(src));
}
__device__ __forceinline__ void mbar_init(uint32_t m, uint32_t cnt) {
    asm volatile("mbarrier.init.shared.b64 [%0], %1;" :: "r"(m), "r"(cnt) : "memory");
}
__device__ __forceinline__ void mbar_arrive(uint32_t m) {
    asm volatile("mbarrier.arrive.shared.b64 _, [%0];" :: "r"(m) : "memory");
}
// Default (no .noinc) semantics: increments the barrier's expected count by 1,
// then arrives once this thread's prior cp.asyncs complete -> NET-NEUTRAL to
// the arrival budget; it only folds cp completion into the barrier.
__device__ __forceinline__ void cp_arrive(uint32_t m) {
    asm volatile("cp.async.mbarrier.arrive.shared.b64 [%0];" :: "r"(m) : "memory");
}
__device__ __forceinline__ void mbar_wait(uint32_t mbar, uint32_t parity) {
    uint32_t done;
    asm volatile(
        "{\n\t"
        ".reg .pred p;\n\t"
        "mbarrier.try_wait.parity.acquire.cta.shared::cta.b64 p, [%1], %2;\n\t"
        "selp.b32 %0, 1, 0, p;\n\t"
        "}"
        : "=r"(done) : "r"(mbar), "r"(parity) : "memory");
    if (!done) {
        asm volatile(
            "{\n\t"
            ".reg .pred P1;\n\t"
            "WL_%=:\n\t"
            "mbarrier.try_wait.parity.acquire.cta.shared::cta.b64 P1, [%0], %1, 0x989680;\n\t"
            "@P1 bra.uni WD_%=;\n\t"
            "bra.uni WL_%=;\n\t"
            "WD_%=:\n\t"
            "}"
            :: "r"(mbar), "r"(parity) : "memory");
    }
}

__device__ __forceinline__ void ldsm_x4(uint32_t* r, uint32_t addr) {
    asm volatile("ldmatrix.sync.aligned.m8n8.x4.shared.b16 {%0,%1,%2,%3}, [%4];"
                 : "=r"(r[0]), "=r"(r[1]), "=r"(r[2]), "=r"(r[3]) : "r"(addr));
}
__device__ __forceinline__ void mma_f16(float c[4],
                                        uint32_t a0, uint32_t a1,
                                        uint32_t a2, uint32_t a3,
                                        uint32_t b0, uint32_t b1)
{
    asm volatile(
        "mma.sync.aligned.m16n8k16.row.col.f32.f16.f16.f32 "
        "{%0,%1,%2,%3}, {%4,%5,%6,%7}, {%8,%9}, {%0,%1,%2,%3};\n"
        : "+f"(c[0]), "+f"(c[1]), "+f"(c[2]), "+f"(c[3])
        : "r"(a0), "r"(a1), "r"(a2), "r"(a3), "r"(b0), "r"(b1));
}

__device__ __forceinline__ uint32_t hsub2(uint32_t a, uint32_t b) {
    uint32_t d;
    asm("sub.rn.f16x2 %0, %1, %2;" : "=r"(d) : "r"(a), "r"(b));
    return d;
}
__device__ __forceinline__ uint32_t hmul2(uint32_t a, uint32_t b) {
    uint32_t d;
    asm("mul.rn.f16x2 %0, %1, %2;" : "=r"(d) : "r"(a), "r"(b));
    return d;
}
__device__ __forceinline__ uint32_t packh2(float lo, float hi) {
    uint32_t d;
    asm("cvt.rn.f16x2.f32 %0, %1, %2;" : "=r"(d) : "f"(hi), "f"(lo));
    return d;
}
// dequant one qword (8 nibbles along k) -> 8 fp16 in k-order, scaled.
// (nib | 0x6400) = fp16(1024+v) exact; -1032 exact; *s rounds once.
__device__ __forceinline__ uint4 dequant8(uint32_t q, uint32_t s2) {
    const uint32_t M = 0x000F000Fu, MG = 0x64006400u, C = 0x64086408u;
    uint32_t t0 = (q & M) | MG;            // {v0, v4}
    uint32_t t1 = ((q >> 4)  & M) | MG;    // {v1, v5}
    uint32_t t2 = ((q >> 8)  & M) | MG;    // {v2, v6}
    uint32_t t3 = ((q >> 12) & M) | MG;    // {v3, v7}
    t0 = hmul2(hsub2(t0, C), s2);
    t1 = hmul2(hsub2(t1, C), s2);
    t2 = hmul2(hsub2(t2, C), s2);
    t3 = hmul2(hsub2(t3, C), s2);
    uint4 o;
    o.x = __byte_perm(t0, t1, 0x5410);     // {w0, w1}
    o.y = __byte_perm(t2, t3, 0x5410);     // {w2, w3}
    o.z = __byte_perm(t0, t1, 0x7632);     // {w4, w5}
    o.w = __byte_perm(t2, t3, 0x7632);     // {w6, w7}
    return o;
}
__device__ __forceinline__ uint32_t scale2h(float s) {
    unsigned short h = __half_as_ushort(__float2half_rn(s));
    return (uint32_t)h * 0x10001u;
}

// ---- pre-pass: X fp32 -> A_half fp16 (one shot) ----------------------------
__global__ __launch_bounds__(256, 8)
void convert_x_kernel(const float* __restrict__ X)
{
    const size_t i = ((size_t)blockIdx.x * 256 + threadIdx.x) * 8;
    const float4* xp = reinterpret_cast<const float4*>(X + i);
    float4 v0 = xp[0], v1 = xp[1];
    uint4 h;
    h.x = packh2(v0.x, v0.y); h.y = packh2(v0.z, v0.w);
    h.z = packh2(v1.x, v1.y); h.w = packh2(v1.z, v1.w);
    *reinterpret_cast<uint4*>(&A_half[i]) = h;
}

__global__ __launch_bounds__(NTH, 1)
void int4_gemm_f16_cpa_kernel(const int*   __restrict__ QW,
                              const float* __restrict__ SC,
                              float*       __restrict__ C)
{
    extern __shared__ char smem[];
    const uint32_t sb = smem_u32(smem);
    char* data = smem + 128;

    const int tid  = threadIdx.x;
    const int wid  = tid >> 5;
    const int lane = tid & 31;
    const int g    = lane >> 2;
    const int t    = lane & 3;
    const int wm   = wid >> 3;               // 0..1
    const int wn   = wid & 7;                // 0..7

    const int m0 = blockIdx.y * BM;
    const int n0 = blockIdx.x * BN;

    // mbarriers: full[s] = sb + 16s, empty[s] = sb + 16s + 8.
    // full count = NTH: per thread one explicit arrive (post-B-STS); the
    // cp_arrive is net-neutral (expect+1, then arrive on cp completion).
    if (tid == 0) {
        #pragma unroll
        for (int s = 0; s < STAGES; s++) {
            mbar_init(sb + 16 * s,     NTH);
            mbar_init(sb + 16 * s + 8, NTH);
        }
    }
    __syncthreads();

    // ---- per-lane LDSM base offsets (bytes), as validated in round 13 --------
    const uint32_t a_lds =
        (uint32_t)((wm * 64 + (lane & 7) + ((lane >> 3) & 1) * 8) * ROWB
                   + ((lane >> 4) & 1) * 16);
    const uint32_t b_lds =
        (uint32_t)((wn * 32 + (lane & 7) + ((lane >> 3) & 1) * 8) * ROWB
                   + ((lane >> 4) & 1) * 16);

    // ---- accumulators: warp 64x32 -> 4(m16) x 4(n8) x 4 = 64 regs -------------
    float acc[4][4][4];
    #pragma unroll
    for (int i = 0; i < 4; i++)
        #pragma unroll
        for (int j = 0; j < 4; j++)
            #pragma unroll
            for (int r = 0; r < 4; r++) acc[i][j][r] = 0.0f;

    // ---- producer mappings -------------------------------------------------------
    // A: thread -> row tid>>2, quarter (tid&3): 8 fp16 = 16B = one cp16
    const int arow = tid >> 2;
    const int aq   = tid & 3;
    const __half* Arow = A_half + (size_t)(m0 + arow) * K_DIM + aq * 8;
    const uint32_t a_sts = (uint32_t)(arow * ROWB + aq * 16);

    // B: thread -> column n0+(tid&255), k-half (tid>>8): 2 qwords -> 2 STS.128
    const int bcol = tid & 255;
    const int bh   = tid >> 8;                // 0/1 -> qweight rows 2bh, 2bh+1
    const int*   QWp = QW + n0 + bcol;
    const float* SCp = SC + n0 + bcol;
    const uint32_t b_sts = (uint32_t)(A_BYTES + bcol * ROWB + bh * 32);

    // ---- prologue: produce tiles 0 and 1 ------------------------------------------
    #pragma unroll
    for (int p = 0; p < AHEAD; p++) {
        cp16(sb + 128u + (uint32_t)(p * STAGE_B) + a_sts, Arow + p * BK);
        cp_arrive(sb + 16 * p);

        const int krow = p * 4 + bh * 2;
        uint32_t q0 = (uint32_t)QWp[(size_t)krow       * N_DIM];
        uint32_t q1 = (uint32_t)QWp[(size_t)(krow + 1) * N_DIM];
        uint32_t s2 = scale2h(SCp[0]);        // tiles 0,1 in group 0

        char* stp = data + p * STAGE_B;
        *reinterpret_cast<uint4*>(stp + b_sts)      = dequant8(q0, s2);
        *reinterpret_cast<uint4*>(stp + b_sts + 16) = dequant8(q1, s2);

        mbar_arrive(sb + 16 * p);   // full (the one counted arrival)
    }

    // held q/scale for tile AHEAD (dequanted next loop iteration)
    uint32_t qh0, qh1;
    float sh;
    {
        const int krow = AHEAD * 4 + bh * 2;
        qh0 = (uint32_t)QWp[(size_t)krow       * N_DIM];
        qh1 = (uint32_t)QWp[(size_t)(krow + 1) * N_DIM];
        sh  = SCp[(size_t)(AHEAD >> 2) * N_DIM];
    }

    // ---- cursors --------------------------------------------------------------------
    int cst = 0, cph = 0;           // consumer: full-wait
    int pst = AHEAD, pph = 1;       // producer: empty-wait (first-lap passes)

    // ---- main loop --------------------------------------------------------------------
    for (int i = 0; i < K_ITERS; i++) {
        const bool do_prod = (i + AHEAD < K_ITERS);

        char* pstage = nullptr;
        uint32_t s2 = 0;
        if (do_prod) {
            s2 = scale2h(sh);
            mbar_wait(sb + 16 * pst + 8, pph);        // stage empty?
            // A tile for i+AHEAD straight from fp16 global via cp.async
            cp16(sb + 128u + (uint32_t)(pst * STAGE_B) + a_sts,
                 Arow + (i + AHEAD) * BK);
            cp_arrive(sb + 16 * pst);
            pstage = data + pst * STAGE_B;
        }

        // prefetch q/scale for tile i+3 (one full iteration of LDG cover)
        uint32_t qn0 = 0, qn1 = 0;
        float sn = 0.0f;
        if (i + AHEAD + 1 < K_ITERS) {
            const int krow = (i + AHEAD + 1) * 4 + bh * 2;
            qn0 = (uint32_t)QWp[(size_t)krow       * N_DIM];
            qn1 = (uint32_t)QWp[(size_t)(krow + 1) * N_DIM];
            sn  = SCp[(size_t)((i + AHEAD + 1) >> 2) * N_DIM];
        }

        mbar_wait(sb + 16 * cst, cph);                // current tile ready

        const uint32_t stb = sb + 128u + (uint32_t)(cst * STAGE_B);
        const uint32_t Ab  = stb + a_lds;
        const uint32_t Bb  = stb + (uint32_t)A_BYTES + b_lds;

        #pragma unroll
        for (int kk = 0; kk < 2; kk++) {              // two k16 steps
            const uint32_t ko = (uint32_t)(kk * 32);

            uint32_t a[4][4];
            #pragma unroll
            for (int ii = 0; ii < 4; ii++)
                ldsm_x4(a[ii], Ab + (uint32_t)(ii * 16 * ROWB) + ko);

            uint32_t b[2][4];
            #pragma unroll
            for (int jp = 0; jp < 2; jp++)
                ldsm_x4(b[jp], Bb + (uint32_t)(jp * 16 * ROWB) + ko);

            #pragma unroll
            for (int ii = 0; ii < 4; ii++)
                #pragma unroll
                for (int jp = 0; jp < 2; jp++)
                    #pragma unroll
                    for (int j2 = 0; j2 < 2; j2++)
                        mma_f16(acc[ii][jp * 2 + j2],
                                a[ii][0], a[ii][1], a[ii][2], a[ii][3],
                                b[jp][j2], b[jp][2 + j2]);

            // interleaved B dequant for tile i+AHEAD (one qword per kk)
            if (do_prod) {
                uint4 o = dequant8(kk ? qh1 : qh0, s2);
                *reinterpret_cast<uint4*>(pstage + b_sts + kk * 16) = o;
            }
        }

        if (do_prod) {
            mbar_arrive(sb + 16 * pst);               // full (release; after STS)
            if (++pst == STAGES) { pst = 0; pph ^= 1; }
            qh0 = qn0; qh1 = qn1; sh = sn;
        }
        mbar_arrive(sb + 16 * cst + 8);               // empty (release)
        if (++cst == STAGES) { cst = 0; cph ^= 1; }
    }

    // ---- writeback (m16n8k16 C layout) -------------------------------------------------
    #pragma unroll
    for (int i = 0; i < 4; i++) {
        int row = m0 + wm * 64 + i * 16 + g;
        #pragma unroll
        for (int j = 0; j < 4; j++) {
            int col = n0 + wn * 32 + j * 8 + 2 * t;
            *reinterpret_cast<float2*>(&C[(size_t)row * N_DIM + col]) =
                make_float2(acc[i][j][0], acc[i][j][1]);
            *reinterpret_cast<float2*>(&C[(size_t)(row + 8) * N_DIM + col]) =
                make_float2(acc[i][j][2], acc[i][j][3]);
        }
    }
}

extern "C" void kernel_launch(void* const* d_in, const int* in_sizes, int n_in,
                              void* d_out, int out_size)
{
    const float* x   = (const float*)d_in[0];
    const int*   qw  = (const int*)d_in[1];
    const float* sc  = (const float*)d_in[2];
    float*       out = (float*)d_out;

    // 1) one-shot fp32 -> fp16 conversion of X into static scratch
    convert_x_kernel<<<(M_DIM * (size_t)K_DIM) / (256 * 8), 256>>>(x);

    // 2) GEMM
    cudaFuncSetAttribute(int4_gemm_f16_cpa_kernel,
                         cudaFuncAttributeMaxDynamicSharedMemorySize, SMEM_BYTES);
    dim3 grid(N_DIM / BN, M_DIM / BM);  // (43, 64)
    int4_gemm_f16_cpa_kernel<<<grid, NTH, SMEM_BYTES>>>(qw, sc, out);
}

// round 16
// speedup vs baseline: 2.1365x; 1.0763x over previous
#include <cuda_runtime.h>
#include <cuda_fp16.h>
#include <cstdint>

// Problem shape (fixed by the dataset):
//   x:       (4, 2048, 4096) fp32  -> M=8192, K=4096 row-major
//   qweight: (512, 11008)   int32  -> 8 int4 nibbles per int32 along K
//   scales:  (32, 11008)    fp32   -> per-group(128) per-out-channel
//   out:     (4, 2048, 11008) fp32
static constexpr int M_DIM = 8192;
static constexpr int K_DIM = 4096;
static constexpr int N_DIM = 11008;

static constexpr int BM = 128;
static constexpr int BN = 256;
static constexpr int BK = 64;
static constexpr int NTH = 512;              // 16 warps: 2(m) x 8(n), tile 64x32
static constexpr int K_ITERS = K_DIM / BK;   // 64
static constexpr int STAGES = 4;
static constexpr int AHEAD = 2;

// fp16 tiles "outer x k": row = 64 fp16 + 8 pad = 72 fp16 = 144 B (36 banks).
// LDSM 8-row windows at banks {(4r+c)%32} -> all 32 banks, conflict-free.
static constexpr int ROWB    = 144;
static constexpr int A_BYTES = BM * ROWB;            // 18432
static constexpr int B_BYTES = BN * ROWB;            // 36864
static constexpr int STAGE_B = A_BYTES + B_BYTES;    // 55296
// smem: [0,64) mbarriers, tile data from byte 128
static constexpr int SMEM_BYTES = 128 + STAGES * STAGE_B;  // 221312

// Pre-converted fp16 copy of X (static scratch; allocation-free).
__device__ __half A_half[(size_t)M_DIM * K_DIM];

__device__ __forceinline__ uint32_t smem_u32(const void* p) {
    uint32_t a;
    asm("{ .reg .u64 t; cvta.to.shared.u64 t, %1; cvt.u32.u64 %0, t; }"
        : "=r"(a) : "l"(p));
    return a;
}
__device__ __forceinline__ void cp16(uint32_t dst, const void* src) {
    asm volatile("cp.async.cg.shared.global [%0], [%1], 16;"
                 :: "r"(dst), "l"(src));
}
__device__ __forceinline__ void mbar_init(uint32_t m, uint32_t cnt) {
    asm volatile("mbarrier.init.shared.b64 [%0], %1;" :: "r"(m), "r"(cnt) : "memory");
}
__device__ __forceinline__ void mbar_arrive(uint32_t m) {
    asm volatile("mbarrier.arrive.shared.b64 _, [%0];" :: "r"(m) : "memory");
}
// Net-neutral to the arrival budget (expect+1, then arrive on cp completion);
// folds this thread's prior cp.asyncs into the barrier.
__device__ __forceinline__ void cp_arrive(uint32_t m) {
    asm volatile("cp.async.mbarrier.arrive.shared.b64 [%0];" :: "r"(m) : "memory");
}
__device__ __forceinline__ void mbar_wait(uint32_t mbar, uint32_t parity) {
    uint32_t done;
    asm volatile(
        "{\n\t"
        ".reg .pred p;\n\t"
        "mbarrier.try_wait.parity.acquire.cta.shared::cta.b64 p, [%1], %2;\n\t"
        "selp.b32 %0, 1, 0, p;\n\t"
        "}"
        : "=r"(done) : "r"(mbar), "r"(parity) : "memory");
    if (!done) {
        asm volatile(
            "{\n\t"
            ".reg .pred P1;\n\t"
            "WL_%=:\n\t"
            "mbarrier.try_wait.parity.acquire.cta.shared::cta.b64 P1, [%0], %1, 0x989680;\n\t"
            "@P1 bra.uni WD_%=;\n\t"
            "bra.uni WL_%=;\n\t"
            "WD_%=:\n\t"
            "}"
            :: "r"(mbar), "r"(parity) : "memory");
    }
}

__device__ __forceinline__ void ldsm_x4(uint32_t* r, uint32_t addr) {
    asm volatile("ldmatrix.sync.aligned.m8n8.x4.shared.b16 {%0,%1,%2,%3}, [%4];"
                 : "=r"(r[0]), "=r"(r[1]), "=r"(r[2]), "=r"(r[3]) : "r"(addr));
}
__device__ __forceinline__ void mma_f16(float c[4],
                                        uint32_t a0, uint32_t a1,
                                        uint32_t a2, uint32_t a3,
                                        uint32_t b0, uint32_t b1)
{
    asm volatile(
        "mma.sync.aligned.m16n8k16.row.col.f32.f16.f16.f32 "
        "{%0,%1,%2,%3}, {%4,%5,%6,%7}, {%8,%9}, {%0,%1,%2,%3};\n"
        : "+f"(c[0]), "+f"(c[1]), "+f"(c[2]), "+f"(c[3])
        : "r"(a0), "r"(a1), "r"(a2), "r"(a3), "r"(b0), "r"(b1));
}

__device__ __forceinline__ uint32_t hsub2(uint32_t a, uint32_t b) {
    uint32_t d;
    asm("sub.rn.f16x2 %0, %1, %2;" : "=r"(d) : "r"(a), "r"(b));
    return d;
}
__device__ __forceinline__ uint32_t hmul2(uint32_t a, uint32_t b) {
    uint32_t d;
    asm("mul.rn.f16x2 %0, %1, %2;" : "=r"(d) : "r"(a), "r"(b));
    return d;
}
__device__ __forceinline__ uint32_t packh2(float lo, float hi) {
    uint32_t d;
    asm("cvt.rn.f16x2.f32 %0, %1, %2;" : "=r"(d) : "f"(hi), "f"(lo));
    return d;
}
// dequant one qword (8 nibbles along k) -> 8 fp16 in k-order, scaled.
// (nib | 0x6400) = fp16(1024+v) exact; -1032 exact; *s rounds once.
__device__ __forceinline__ uint4 dequant8(uint32_t q, uint32_t s2) {
    const uint32_t M = 0x000F000Fu, MG = 0x64006400u, C = 0x64086408u;
    uint32_t t0 = (q & M) | MG;            // {v0, v4}
    uint32_t t1 = ((q >> 4)  & M) | MG;    // {v1, v5}
    uint32_t t2 = ((q >> 8)  & M) | MG;    // {v2, v6}
    uint32_t t3 = ((q >> 12) & M) | MG;    // {v3, v7}
    t0 = hmul2(hsub2(t0, C), s2);
    t1 = hmul2(hsub2(t1, C), s2);
    t2 = hmul2(hsub2(t2, C), s2);
    t3 = hmul2(hsub2(t3, C), s2);
    uint4 o;
    o.x = __byte_perm(t0, t1, 0x5410);     // {w0, w1}
    o.y = __byte_perm(t2, t3, 0x5410);     // {w2, w3}
    o.z = __byte_perm(t0, t1, 0x7632);     // {w4, w5}
    o.w = __byte_perm(t2, t3, 0x7632);     // {w6, w7}
    return o;
}
__device__ __forceinline__ uint32_t scale2h(float s) {
    unsigned short h = __half_as_ushort(__float2half_rn(s));
    return (uint32_t)h * 0x10001u;
}

// ---- pre-pass: X fp32 -> A_half fp16 (one shot) ----------------------------
__global__ __launch_bounds__(256, 8)
void convert_x_kernel(const float* __restrict__ X)
{
    const size_t i = ((size_t)blockIdx.x * 256 + threadIdx.x) * 8;
    const float4* xp = reinterpret_cast<const float4*>(X + i);
    float4 v0 = xp[0], v1 = xp[1];
    uint4 h;
    h.x = packh2(v0.x, v0.y); h.y = packh2(v0.z, v0.w);
    h.z = packh2(v1.x, v1.y); h.w = packh2(v1.z, v1.w);
    *reinterpret_cast<uint4*>(&A_half[i]) = h;
}

__global__ __launch_bounds__(NTH, 1)
void int4_gemm_f16_bk64_kernel(const int*   __restrict__ QW,
                               const float* __restrict__ SC,
                               float*       __restrict__ C)
{
    extern __shared__ char smem[];
    const uint32_t sb = smem_u32(smem);
    char* data = smem + 128;

    const int tid  = threadIdx.x;
    const int wid  = tid >> 5;
    const int lane = tid & 31;
    const int g    = lane >> 2;
    const int t    = lane & 3;
    const int wm   = wid >> 3;               // 0..1
    const int wn   = wid & 7;                // 0..7

    const int m0 = blockIdx.y * BM;
    const int n0 = blockIdx.x * BN;

    // mbarriers: full[s] = sb + 16s (count NTH: one explicit arrive per thread
    // per production; cp_arrive is net-neutral), empty[s] = sb + 16s + 8.
    if (tid == 0) {
        #pragma unroll
        for (int s = 0; s < STAGES; s++) {
            mbar_init(sb + 16 * s,     NTH);
            mbar_init(sb + 16 * s + 8, NTH);
        }
    }
    __syncthreads();

    // ---- per-lane LDSM base offsets (bytes) ------------------------------------
    const uint32_t a_lds =
        (uint32_t)((wm * 64 + (lane & 7) + ((lane >> 3) & 1) * 8) * ROWB
                   + ((lane >> 4) & 1) * 16);
    const uint32_t b_lds =
        (uint32_t)((wn * 32 + (lane & 7) + ((lane >> 3) & 1) * 8) * ROWB
                   + ((lane >> 4) & 1) * 16);

    // ---- accumulators: warp 64x32 -> 4(m16) x 4(n8) x 4 = 64 regs ---------------
    float acc[4][4][4];
    #pragma unroll
    for (int i = 0; i < 4; i++)
        #pragma unroll
        for (int j = 0; j < 4; j++)
            #pragma unroll
            for (int r = 0; r < 4; r++) acc[i][j][r] = 0.0f;

    // ---- producer mappings ---------------------------------------------------------
    // A: thread -> row tid>>2, quarter (tid&3)*16 fp16 = 32B -> 2 cp16
    const int arow = tid >> 2;
    const int aq   = tid & 3;
    const __half* Arow = A_half + (size_t)(m0 + arow) * K_DIM + aq * 16;
    const uint32_t a_sts = (uint32_t)(arow * ROWB + aq * 32);

    // B: thread -> column n0+(tid&255), k-half (tid>>8): 4 qwords -> 4 STS.128
    const int bcol = tid & 255;
    const int bh   = tid >> 8;                // 0/1 -> k local 32bh..32bh+31
    const int*   QWp = QW + n0 + bcol;
    const float* SCp = SC + n0 + bcol;
    const uint32_t b_sts = (uint32_t)(A_BYTES + bcol * ROWB + bh * 64);

    // ---- prologue: produce tiles 0 and 1 ---------------------------------------------
    #pragma unroll
    for (int p = 0; p < AHEAD; p++) {
        const uint32_t ad = sb + 128u + (uint32_t)(p * STAGE_B) + a_sts;
        cp16(ad,       Arow + p * BK);
        cp16(ad + 16u, Arow + p * BK + 8);
        cp_arrive(sb + 16 * p);

        const int krow = p * 8 + bh * 4;
        uint32_t s2 = scale2h(SCp[0]);        // tiles 0,1 in group 0
        char* stp = data + p * STAGE_B;
        #pragma unroll
        for (int qq = 0; qq < 4; qq++) {
            uint32_t q = (uint32_t)QWp[(size_t)(krow + qq) * N_DIM];
            *reinterpret_cast<uint4*>(stp + b_sts + qq * 16) = dequant8(q, s2);
        }
        mbar_arrive(sb + 16 * p);   // full (the one counted arrival)
    }

    // held qwords/scale for tile AHEAD
    uint32_t qh[4];
    float sh;
    {
        const int krow = AHEAD * 8 + bh * 4;
        #pragma unroll
        for (int qq = 0; qq < 4; qq++)
            qh[qq] = (uint32_t)QWp[(size_t)(krow + qq) * N_DIM];
        sh = SCp[(size_t)(AHEAD >> 1) * N_DIM];
    }

    // ---- cursors -----------------------------------------------------------------------
    int cst = 0, cph = 0;           // consumer: full-wait
    int pst = AHEAD, pph = 1;       // producer: empty-wait (first-lap passes)

    // ---- main loop -----------------------------------------------------------------------
    for (int i = 0; i < K_ITERS; i++) {
        const bool do_prod = (i + AHEAD < K_ITERS);

        char* pstage = nullptr;
        uint32_t s2 = 0;
        if (do_prod) {
            s2 = scale2h(sh);
            mbar_wait(sb + 16 * pst + 8, pph);        // stage empty?
            const uint32_t ad = sb + 128u + (uint32_t)(pst * STAGE_B) + a_sts;
            const __half* ap = Arow + (i + AHEAD) * BK;
            cp16(ad,       ap);
            cp16(ad + 16u, ap + 8);
            cp_arrive(sb + 16 * pst);
            pstage = data + pst * STAGE_B;
        }

        // prefetch qwords/scale for tile i+3 (a full iteration of LDG cover)
        uint32_t qn[4] = {0, 0, 0, 0};
        float sn = 0.0f;
        if (i + AHEAD + 1 < K_ITERS) {
            const int krow = (i + AHEAD + 1) * 8 + bh * 4;
            #pragma unroll
            for (int qq = 0; qq < 4; qq++)
                qn[qq] = (uint32_t)QWp[(size_t)(krow + qq) * N_DIM];
            sn = SCp[(size_t)((i + AHEAD + 1) >> 1) * N_DIM];
        }

        mbar_wait(sb + 16 * cst, cph);                // current tile ready

        const uint32_t stb = sb + 128u + (uint32_t)(cst * STAGE_B);
        const uint32_t Ab  = stb + a_lds;
        const uint32_t Bb  = stb + (uint32_t)A_BYTES + b_lds;

        #pragma unroll
        for (int kk = 0; kk < 4; kk++) {              // four k16 steps
            const uint32_t ko = (uint32_t)(kk * 32);

            uint32_t a[4][4];
            #pragma unroll
            for (int ii = 0; ii < 4; ii++)
                ldsm_x4(a[ii], Ab + (uint32_t)(ii * 16 * ROWB) + ko);

            uint32_t b[2][4];
            #pragma unroll
            for (int jp = 0; jp < 2; jp++)
                ldsm_x4(b[jp], Bb + (uint32_t)(jp * 16 * ROWB) + ko);

            #pragma unroll
            for (int ii = 0; ii < 4; ii++)
                #pragma unroll
                for (int jp = 0; jp < 2; jp++)
                    #pragma unroll
                    for (int j2 = 0; j2 < 2; j2++)
                        mma_f16(acc[ii][jp * 2 + j2],
                                a[ii][0], a[ii][1], a[ii][2], a[ii][3],
                                b[jp][j2], b[jp][2 + j2]);

            // interleaved B dequant for tile i+AHEAD (one qword per kk)
            if (do_prod) {
                uint4 o = dequant8(qh[kk], s2);
                *reinterpret_cast<uint4*>(pstage + b_sts + kk * 16) = o;
            }
        }

        if (do_prod) {
            mbar_arrive(sb + 16 * pst);               // full (release; after STS)
            if (++pst == STAGES) { pst = 0; pph ^= 1; }
            #pragma unroll
            for (int qq = 0; qq < 4; qq++) qh[qq] = qn[qq];
            sh = sn;
        }
        mbar_arrive(sb + 16 * cst + 8);               // empty (release)
        if (++cst == STAGES) { cst = 0; cph ^= 1; }
    }

    // ---- writeback (m16n8k16 C layout) ----------------------------------------------------
    #pragma unroll
    for (int i = 0; i < 4; i++) {
        int row = m0 + wm * 64 + i * 16 + g;
        #pragma unroll
        for (int j = 0; j < 4; j++) {
            int col = n0 + wn * 32 + j * 8 + 2 * t;
            *reinterpret_cast<float2*>(&C[(size_t)row * N_DIM + col]) =
                make_float2(acc[i][j][0], acc[i][j][1]);
            *reinterpret_cast<float2*>(&C[(size_t)(row + 8) * N_DIM + col]) =
                make_float2(acc[i][j][2], acc[i][j][3]);
        }
    }
}

extern "C" void kernel_launch(void* const* d_in, const int* in_sizes, int n_in,
                              void* d_out, int out_size)
{
    const float* x   = (const float*)d_in[0];
    const int*   qw  = (const int*)d_in[1];
    const float* sc  = (const float*)d_in[2];
    float*       out = (float*)d_out;

    // 1) one-shot fp32 -> fp16 conversion of X into static scratch
    convert_x_kernel<<<(M_DIM * (size_t)K_DIM) / (256 * 8), 256>>>(x);

    // 2) GEMM
    cudaFuncSetAttribute(int4_gemm_f16_bk64_kernel,
                         cudaFuncAttributeMaxDynamicSharedMemorySize, SMEM_BYTES);
    dim3 grid(N_DIM / BN, M_DIM / BM);  // (43, 64)
    int4_gemm_f16_bk64_kernel<<<grid, NTH, SMEM_BYTES>>>(qw, sc, out);
}